// round 3
// baseline (speedup 1.0000x reference)
#include <cuda_runtime.h>
#include <cstdint>

#define D_DIM   128
#define K_CODES 1024
#define N_MAX   131072
#define BM      128
#define BN      128
#define NTHR    256
#define XP      129   // xs pitch (pad to cut store conflicts to 4-way)
#define CP      128   // cs pitch (loads are conflict-free, float4-aligned)

// -------- device scratch (no allocations allowed) --------
__device__ int   g_idx[N_MAX];
__device__ float g_cnorm[K_CODES];
__device__ float g_cbT[D_DIM * K_CODES];   // codebook transposed, d-major
__device__ float g_sse;

// XLA warp row-reduce: shfl_down tree, offsets 16/8/4/2/1, fp32 add each step.
__device__ __forceinline__ float xla_warp_reduce_add(float v) {
    v = __fadd_rn(v, __shfl_down_sync(0xFFFFFFFFu, v, 16));
    v = __fadd_rn(v, __shfl_down_sync(0xFFFFFFFFu, v, 8));
    v = __fadd_rn(v, __shfl_down_sync(0xFFFFFFFFu, v, 4));
    v = __fadd_rn(v, __shfl_down_sync(0xFFFFFFFFu, v, 2));
    v = __fadd_rn(v, __shfl_down_sync(0xFFFFFFFFu, v, 1));
    return v;   // lane 0 holds the XLA-ordered sum
}

// ============================================================
// K0: c_norm (XLA row-reduce emulation) + transpose codebook.
// One warp per code row.
// ============================================================
__global__ void prep_kernel(const float* __restrict__ cb) {
    if (blockIdx.x == 0 && threadIdx.x == 0) g_sse = 0.0f;
    int lane  = threadIdx.x & 31;
    int code  = blockIdx.x * (blockDim.x >> 5) + (threadIdx.x >> 5);
    if (code >= K_CODES) return;
    const float* row = cb + (size_t)code * D_DIM;

    // transpose (float4 path, layout only — no arithmetic)
    const float4* row4 = (const float4*)row;
    float4 v = row4[lane];
    g_cbT[(lane * 4 + 0) * K_CODES + code] = v.x;
    g_cbT[(lane * 4 + 1) * K_CODES + code] = v.y;
    g_cbT[(lane * 4 + 2) * K_CODES + code] = v.z;
    g_cbT[(lane * 4 + 3) * K_CODES + code] = v.w;

    // c_norm: lane t handles elements t, t+32, t+64, t+96 sequentially
    float e0 = row[lane], e1 = row[lane + 32], e2 = row[lane + 64], e3 = row[lane + 96];
    float p = __fmul_rn(e0, e0);
    p = __fadd_rn(p, __fmul_rn(e1, e1));
    p = __fadd_rn(p, __fmul_rn(e2, e2));
    p = __fadd_rn(p, __fmul_rn(e3, e3));
    float s = xla_warp_reduce_add(p);
    if (lane == 0) g_cnorm[code] = s;
}

// ============================================================
// KA: fused scores-GEMM (fp32 FFMA chain, d ascending = cublas SGEMM order)
//     + reference-faithful quantized dist + first-index argmin.
// ============================================================
__global__ __launch_bounds__(NTHR, 1)
void argmin_kernel(const float* __restrict__ x) {
    extern __shared__ float smem[];
    float* xs = smem;                                   // [D][XP]
    float* cs = smem + D_DIM * XP;                      // [D][CP]
    float* cn = smem + D_DIM * XP + D_DIM * CP;         // [BN]
    float* xn = cn + BN;                                // [BM]

    const int tid = threadIdx.x;
    const int tx  = tid & 15;            // code group
    const int ty  = tid >> 4;            // row  group
    const int lane = tid & 31, warp = tid >> 5;
    const size_t row0 = (size_t)blockIdx.x * BM;

    // ---- load x tile, transposed into xs[d][r] ----
    const float4* x4 = (const float4*)(x + row0 * D_DIM);
    for (int i = tid; i < BM * (D_DIM / 4); i += NTHR) {
        int r = i >> 5, d4 = i & 31;
        float4 v = x4[r * (D_DIM / 4) + d4];
        xs[(d4 * 4 + 0) * XP + r] = v.x;
        xs[(d4 * 4 + 1) * XP + r] = v.y;
        xs[(d4 * 4 + 2) * XP + r] = v.z;
        xs[(d4 * 4 + 3) * XP + r] = v.w;
    }
    __syncthreads();

    // ---- x_norm per row, XLA row-reduce emulation (warp w: rows 16w..16w+15) ----
    for (int k = 0; k < 16; k++) {
        int r = warp * 16 + k;
        float e0 = xs[lane * XP + r];
        float e1 = xs[(lane + 32) * XP + r];
        float e2 = xs[(lane + 64) * XP + r];
        float e3 = xs[(lane + 96) * XP + r];
        float p = __fmul_rn(e0, e0);
        p = __fadd_rn(p, __fmul_rn(e1, e1));
        p = __fadd_rn(p, __fmul_rn(e2, e2));
        p = __fadd_rn(p, __fmul_rn(e3, e3));
        float s = xla_warp_reduce_add(p);
        if (lane == 0) xn[r] = s;
    }

    float best[8];
    int   bidx[8];
    #pragma unroll
    for (int i = 0; i < 8; i++) { best[i] = 3.4e38f; bidx[i] = 0x7FFFFFFF; }

    for (int t = 0; t < K_CODES / BN; t++) {
        for (int i = tid; i < D_DIM * (BN / 4); i += NTHR) {
            int d = i >> 5, c4 = i & 31;
            float4 v = *(const float4*)&g_cbT[d * K_CODES + t * BN + c4 * 4];
            *(float4*)&cs[d * CP + c4 * 4] = v;
        }
        if (tid < BN) cn[tid] = g_cnorm[t * BN + tid];
        __syncthreads();   // also covers xn writes on t==0

        float acc[8][8];
        #pragma unroll
        for (int i = 0; i < 8; i++)
            #pragma unroll
            for (int j = 0; j < 8; j++) acc[i][j] = 0.0f;

        #pragma unroll 2
        for (int d = 0; d < D_DIM; d++) {
            float xf[8], cf[8];
            #pragma unroll
            for (int i = 0; i < 8; i++) xf[i] = xs[d * XP + ty + 16 * i];
            #pragma unroll
            for (int j = 0; j < 8; j++) cf[j] = cs[d * CP + tx + 16 * j];
            #pragma unroll
            for (int i = 0; i < 8; i++)
                #pragma unroll
                for (int j = 0; j < 8; j++)
                    acc[i][j] = fmaf(xf[i], cf[j], acc[i][j]);   // d-ascending chain
        }

        // ---- reference-faithful quantized dist + running first-index argmin ----
        #pragma unroll
        for (int j = 0; j < 8; j++) {
            float cnj  = cn[tx + 16 * j];
            int   code = t * BN + tx + 16 * j;
            #pragma unroll
            for (int i = 0; i < 8; i++) {
                float xni  = xn[ty + 16 * i];
                float tt   = __fadd_rn(xni, cnj);              // fl(xn + cn)
                float u    = __fmul_rn(2.0f, acc[i][j]);       // exact
                float dist = fmaxf(__fadd_rn(tt, -u), 0.0f);   // fl(t - 2s), clamp
                if (dist < best[i]) { best[i] = dist; bidx[i] = code; }
            }
        }
        __syncthreads();
    }

    // ---- cross-thread reduction (16 candidates per row), lexicographic ----
    float* rv = cs;
    int*   ri = (int*)(cs + BM * 16);
    #pragma unroll
    for (int i = 0; i < 8; i++) {
        int r = ty + 16 * i;
        rv[r * 16 + tx] = best[i];
        ri[r * 16 + tx] = bidx[i];
    }
    __syncthreads();
    if (tid < BM) {
        float bv = rv[tid * 16];
        int   bi = ri[tid * 16];
        #pragma unroll
        for (int k = 1; k < 16; k++) {
            float v  = rv[tid * 16 + k];
            int   id = ri[tid * 16 + k];
            if (v < bv || (v == bv && id < bi)) { bv = v; bi = id; }
        }
        g_idx[row0 + tid] = bi;
    }
}

// ============================================================
// KB: gather z, emit z_st = fl(x + fl(z - x)), accumulate SSE
// ============================================================
__global__ void gather_kernel(const float* __restrict__ x,
                              const float* __restrict__ cb,
                              float* __restrict__ out, int n) {
    int i4 = blockIdx.x * blockDim.x + threadIdx.x;
    float local = 0.0f;
    int total4 = n * (D_DIM / 4);
    if (i4 < total4) {
        int row = i4 >> 5;
        int c4  = i4 & 31;
        int idx = g_idx[row];
        float4 cv = ((const float4*)cb)[idx * (D_DIM / 4) + c4];
        float4 xv = ((const float4*)x)[i4];
        float dx = __fadd_rn(cv.x, -xv.x);
        float dy = __fadd_rn(cv.y, -xv.y);
        float dz = __fadd_rn(cv.z, -xv.z);
        float dw = __fadd_rn(cv.w, -xv.w);
        float4 ov;
        ov.x = __fadd_rn(xv.x, dx);
        ov.y = __fadd_rn(xv.y, dy);
        ov.z = __fadd_rn(xv.z, dz);
        ov.w = __fadd_rn(xv.w, dw);
        ((float4*)out)[i4] = ov;
        local = dx * dx + dy * dy + dz * dz + dw * dw;
    }
    #pragma unroll
    for (int off = 16; off; off >>= 1) local += __shfl_xor_sync(0xFFFFFFFFu, local, off);
    __shared__ float red[8];
    int lane = threadIdx.x & 31, warp = threadIdx.x >> 5;
    if (lane == 0) red[warp] = local;
    __syncthreads();
    if (warp == 0) {
        float v = (lane < 8) ? red[lane] : 0.0f;
        #pragma unroll
        for (int off = 4; off; off >>= 1) v += __shfl_xor_sync(0xFFFFFFFFu, v, off);
        if (lane == 0) atomicAdd(&g_sse, v);
    }
}

// ============================================================
// KC: histogram -> perplexity; write the 3 scalars
// ============================================================
__global__ void finalize_kernel(float* __restrict__ out, int n, long scalar_off) {
    __shared__ int   cnt[K_CODES];
    __shared__ float rs[32];
    int tid = threadIdx.x;
    for (int i = tid; i < K_CODES; i += blockDim.x) cnt[i] = 0;
    __syncthreads();
    for (int i = tid; i < n; i += blockDim.x) atomicAdd(&cnt[g_idx[i]], 1);
    __syncthreads();
    float local = 0.0f;
    float invn = 1.0f / (float)n;   // n = 2^17 -> exact
    for (int i = tid; i < K_CODES; i += blockDim.x) {
        float p = __fmul_rn((float)cnt[i], invn);
        local += p * logf(__fadd_rn(p, 1e-10f));
    }
    #pragma unroll
    for (int off = 16; off; off >>= 1) local += __shfl_xor_sync(0xFFFFFFFFu, local, off);
    int lane = tid & 31, warp = tid >> 5;
    if (lane == 0) rs[warp] = local;
    __syncthreads();
    if (warp == 0) {
        float v = (lane < (int)(blockDim.x >> 5)) ? rs[lane] : 0.0f;
        #pragma unroll
        for (int off = 16; off; off >>= 1) v += __shfl_xor_sync(0xFFFFFFFFu, v, off);
        if (lane == 0) {
            float loss = g_sse / (float)((long)n * D_DIM);
            out[scalar_off + 0] = loss;        // quantization_loss
            out[scalar_off + 1] = loss;        // commitment_loss
            out[scalar_off + 2] = expf(-v);    // perplexity
        }
    }
}

// ============================================================
extern "C" void kernel_launch(void* const* d_in, const int* in_sizes, int n_in,
                              void* d_out, int out_size) {
    const float* x  = (const float*)d_in[0];
    const float* cb = (const float*)d_in[1];
    float* out = (float*)d_out;

    int nx = in_sizes[0];
    int n  = nx / D_DIM;

    constexpr int SMEM_KA = (D_DIM * XP + D_DIM * CP + BN + BM) * (int)sizeof(float);
    cudaFuncSetAttribute(argmin_kernel, cudaFuncAttributeMaxDynamicSharedMemorySize, SMEM_KA);

    prep_kernel<<<K_CODES / 8, 256>>>(cb);
    argmin_kernel<<<n / BM, NTHR, SMEM_KA>>>(x);
    gather_kernel<<<(n * (D_DIM / 4) + 255) / 256, 256>>>(x, cb, out, n);
    finalize_kernel<<<1, 1024>>>(out, n, (long)nx);
}